// round 5
// baseline (speedup 1.0000x reference)
#include <cuda_runtime.h>
#include <math.h>

#define BATCH 32
#define HDIM  64
#define WDIM  64
#define HW    4096
#define KPTS  17

// ---------------- scratch (device globals; no allocations allowed) ----------
__device__ float g_bufA[(size_t)32 * 256 * 4096];
__device__ float g_bufB[(size_t)32 * 256 * 4096];
__device__ float g_cg[BATCH * KPTS * 2];

// ---------------- conv3x3 (SAME) + BN + ReLU --------------------------------
// Block tile: 64 cout x (4 rows x 64 cols). 8 cin per chunk.
// Per thread: 8 cout x 8 cols of one row -> 64 accumulators.
__global__ __launch_bounds__(256, 2)
void conv3x3_bn_relu(const float* __restrict__ in, const float* __restrict__ w,
                     const float* __restrict__ gam, const float* __restrict__ bet,
                     float* __restrict__ out, int Cin, int Cout)
{
    __shared__ float s_in[8][6][67];   // [cin][row -1..4][col -1..64], pad 67
    __shared__ float s_w[8][9][65];    // [cin][tap][cout], pad 65

    const int tid      = threadIdx.x;
    const int rowBase  = blockIdx.x * 4;
    const int coutBase = blockIdx.y * 64;
    const int b        = blockIdx.z;

    const int g   = tid & 31;         // 32 pixel-groups
    const int rt  = g >> 3;           // row in 4-row tile
    const int c0  = (g & 7) * 8;      // col base (8 cols per thread)
    const int oc0 = (tid >> 5) * 8;   // cout base (8 couts per thread)

    float acc[8][8];
#pragma unroll
    for (int i = 0; i < 8; i++)
#pragma unroll
        for (int j = 0; j < 8; j++) acc[i][j] = 0.f;

    const float* inB = in + (size_t)b * Cin * HW;

    for (int cb = 0; cb < Cin; cb += 8) {
        __syncthreads();
        // load input chunk: 8 cin x 6 rows x 66 cols (zero-padded border)
        for (int idx = tid; idx < 8 * 6 * 66; idx += 256) {
            int cin = idx / 396;
            int rem = idx - cin * 396;
            int r   = rem / 66;
            int c   = rem - r * 66;
            int gy  = rowBase + r - 1;
            int gx  = c - 1;
            float v = 0.f;
            if ((unsigned)gy < 64u && (unsigned)gx < 64u)
                v = inB[(size_t)(cb + cin) * HW + gy * 64 + gx];
            s_in[cin][r][c] = v;
        }
        // load weight chunk: 64 cout x 8 cin x 9 taps
        for (int idx = tid; idx < 64 * 72; idx += 256) {
            int co  = idx / 72;
            int r   = idx - co * 72;
            int cin = r / 9;
            int tap = r - cin * 9;
            s_w[cin][tap][co] =
                w[((size_t)(coutBase + co) * Cin + (cb + cin)) * 9 + tap];
        }
        __syncthreads();

#pragma unroll 1
        for (int cin = 0; cin < 8; ++cin) {
#pragma unroll
            for (int dy = 0; dy < 3; ++dy) {
                float iv[10];
#pragma unroll
                for (int t = 0; t < 10; t++) iv[t] = s_in[cin][rt + dy][c0 + t];
#pragma unroll
                for (int dx = 0; dx < 3; ++dx) {
                    float wv[8];
#pragma unroll
                    for (int i = 0; i < 8; i++) wv[i] = s_w[cin][dy * 3 + dx][oc0 + i];
#pragma unroll
                    for (int i = 0; i < 8; i++)
#pragma unroll
                        for (int j = 0; j < 8; j++)
                            acc[i][j] = fmaf(wv[i], iv[j + dx], acc[i][j]);
                }
            }
        }
    }

    // epilogue: BN (var=1.0 + eps) + ReLU
    const float inv = rsqrtf(1.0f + 1e-5f);
#pragma unroll
    for (int i = 0; i < 8; i++) {
        int co   = coutBase + oc0 + i;
        float sc = gam[co] * inv;
        float bi = bet[co];
        float* op = out + ((size_t)b * Cout + co) * HW + (rowBase + rt) * 64 + c0;
#pragma unroll
        for (int j = 0; j < 8; j++) {
            float v = fmaf(acc[i][j], sc, bi);
            op[j] = v > 0.f ? v : 0.f;
        }
    }
}

// ---------------- conv1x1 + bias (+ optional softplus) ----------------------
// MODE 0: out = conv + bias.  MODE 1: out = softplus(conv + bias).
template <int CIN, int COUT, int MODE>
__global__ __launch_bounds__(256)
void conv1x1_epi(const float* __restrict__ in, const float* __restrict__ w,
                 const float* __restrict__ bias, float* __restrict__ out)
{
    __shared__ float s_w[COUT * CIN];
    const int tid = threadIdx.x;
    for (int i = tid; i < COUT * CIN; i += 256) s_w[i] = w[i];
    __syncthreads();

    const int p = blockIdx.x * 256 + tid;   // pixel in image
    const int b = blockIdx.y;

    float acc[COUT];
#pragma unroll
    for (int k = 0; k < COUT; k++) acc[k] = 0.f;

    const float* ip = in + (size_t)b * CIN * HW + p;
#pragma unroll 4
    for (int c = 0; c < CIN; c++) {
        float v = ip[(size_t)c * HW];
#pragma unroll
        for (int k = 0; k < COUT; k++) acc[k] = fmaf(v, s_w[k * CIN + c], acc[k]);
    }

#pragma unroll
    for (int k = 0; k < COUT; k++) {
        float v = acc[k] + bias[k];
        if (MODE == 1) v = fmaxf(v, 0.f) + log1pf(expf(-fabsf(v)));
        out[((size_t)b * COUT + k) * HW + p] = v;
    }
}

// ---------------- soft-argmax over 64x64 heatmap per (b,k) ------------------
__global__ void soft_argmax_kernel(const float* __restrict__ heat,
                                   float* __restrict__ cg,
                                   float* __restrict__ scores)
{
    const int bk  = blockIdx.x;
    const int tid = threadIdx.x;
    const float* h = heat + (size_t)bk * HW;

    __shared__ float rs0[256], rs1[256], rs2[256];

    float m = -INFINITY;
    for (int p = tid; p < HW; p += 256) m = fmaxf(m, h[p]);
    rs0[tid] = m;
    __syncthreads();
    for (int s = 128; s > 0; s >>= 1) {
        if (tid < s) rs0[tid] = fmaxf(rs0[tid], rs0[tid + s]);
        __syncthreads();
    }
    const float mx = rs0[0];
    __syncthreads();

    float se = 0.f, sx = 0.f, sy = 0.f;
    for (int p = tid; p < HW; p += 256) {
        float e = expf(h[p] - mx);
        se += e;
        sx += e * (float)(p & 63);
        sy += e * (float)(p >> 6);
    }
    rs0[tid] = se; rs1[tid] = sx; rs2[tid] = sy;
    __syncthreads();
    for (int s = 128; s > 0; s >>= 1) {
        if (tid < s) {
            rs0[tid] += rs0[tid + s];
            rs1[tid] += rs1[tid + s];
            rs2[tid] += rs2[tid + s];
        }
        __syncthreads();
    }
    if (tid == 0) {
        scores[bk]     = mx;
        cg[2 * bk]     = rs1[0] / rs0[0];
        cg[2 * bk + 1] = rs2[0] / rs0[0];
    }
}

// ---------------- local refine + combine + offset sampling ------------------
__global__ void finalize_kernel(const float* __restrict__ heat,
                                const float* __restrict__ off,
                                const float* __restrict__ cg,
                                const float* __restrict__ alpha_p,
                                const float* __restrict__ fusion_p,
                                float* __restrict__ coords,
                                float* __restrict__ fw_out)
{
    const int t = blockIdx.x * blockDim.x + threadIdx.x;
    const float fwv = 1.f / (1.f + expf(-fusion_p[0]));
    if (t == 0) fw_out[0] = fwv;
    if (t >= BATCH * KPTS) return;

    const float a   = 1.f / (1.f + expf(-alpha_p[0]));
    const float cgx = cg[2 * t];
    const float cgy = cg[2 * t + 1];
    const int px = (int)rintf(fminf(fmaxf(cgx, 0.f), 63.f));
    const int py = (int)rintf(fminf(fmaxf(cgy, 0.f), 63.f));

    const float* h = heat + (size_t)t * HW;

    float mx = -INFINITY;
    for (int i = 0; i < 5; i++) {
        int ys = py + i - 2; if ((unsigned)ys >= 64u) continue;
        for (int j = 0; j < 5; j++) {
            int xs = px + j - 2; if ((unsigned)xs >= 64u) continue;
            mx = fmaxf(mx, h[ys * 64 + xs]);
        }
    }
    float sw = 0.f, sxw = 0.f, syw = 0.f;
    for (int i = 0; i < 5; i++) {
        int ys = py + i - 2; if ((unsigned)ys >= 64u) continue;
        for (int j = 0; j < 5; j++) {
            int xs = px + j - 2; if ((unsigned)xs >= 64u) continue;
            float e = expf(h[ys * 64 + xs] - mx);
            sw  += e;
            sxw += e * (float)xs;
            syw += e * (float)ys;
        }
    }
    const float rx = sxw / sw;
    const float ry = syw / sw;

    float cx = a * cgx + (1.f - a) * rx;
    float cy = a * cgy + (1.f - a) * ry;

    // bilinear sample of the 2 offset channels at (cx, cy)
    const float ix = fminf(fmaxf(cx, 0.f), 63.f);
    const float iy = fminf(fmaxf(cy, 0.f), 63.f);
    const float x0 = floorf(ix), y0 = floorf(iy);
    const float wx = ix - x0,  wy = iy - y0;
    const int x0i = min(max((int)x0, 0), 63);
    const int x1i = min(x0i + 1, 63);
    const int y0i = min(max((int)y0, 0), 63);
    const int y1i = min(y0i + 1, 63);

    const float* o0 = off + (size_t)(t * 2) * HW;   // channel k*2+0
    const float* o1 = o0 + HW;                      // channel k*2+1

    float a00 = o0[y0i * 64 + x0i], a01 = o0[y0i * 64 + x1i];
    float a10 = o0[y1i * 64 + x0i], a11 = o0[y1i * 64 + x1i];
    float v0 = (1.f - wy) * ((1.f - wx) * a00 + wx * a01)
             +        wy  * ((1.f - wx) * a10 + wx * a11);

    a00 = o1[y0i * 64 + x0i]; a01 = o1[y0i * 64 + x1i];
    a10 = o1[y1i * 64 + x0i]; a11 = o1[y1i * 64 + x1i];
    float v1 = (1.f - wy) * ((1.f - wx) * a00 + wx * a01)
             +        wy  * ((1.f - wx) * a10 + wx * a11);

    coords[2 * t]     = cx + fwv * v0;
    coords[2 * t + 1] = cy + fwv * v1;
}

// ---------------- launch ----------------------------------------------------
extern "C" void kernel_launch(void* const* d_in, const int* in_sizes, int n_in,
                              void* d_out, int out_size)
{
    const float* x    = (const float*)d_in[0];
    const float* w_s1 = (const float*)d_in[1];
    const float* g_s1 = (const float*)d_in[2];
    const float* b_s1 = (const float*)d_in[3];
    const float* w_s2 = (const float*)d_in[4];
    const float* g_s2 = (const float*)d_in[5];
    const float* b_s2 = (const float*)d_in[6];
    const float* w_h1 = (const float*)d_in[7];
    const float* g_h1 = (const float*)d_in[8];
    const float* b_h1 = (const float*)d_in[9];
    const float* w_h2 = (const float*)d_in[10];
    const float* c_h2 = (const float*)d_in[11];
    const float* w_o1 = (const float*)d_in[12];
    const float* g_o1 = (const float*)d_in[13];
    const float* b_o1 = (const float*)d_in[14];
    const float* w_o2 = (const float*)d_in[15];
    const float* c_o2 = (const float*)d_in[16];
    const float* w_v1 = (const float*)d_in[17];
    const float* g_v1 = (const float*)d_in[18];
    const float* b_v1 = (const float*)d_in[19];
    const float* w_v2 = (const float*)d_in[20];
    const float* c_v2 = (const float*)d_in[21];
    const float* alpha  = (const float*)d_in[22];
    const float* fusion = (const float*)d_in[23];

    float *bufA, *bufB, *cg;
    cudaGetSymbolAddress((void**)&bufA, g_bufA);
    cudaGetSymbolAddress((void**)&bufB, g_bufB);
    cudaGetSymbolAddress((void**)&cg,   g_cg);

    float* out    = (float*)d_out;
    float* heat   = out;                 // 32*17*4096      = 2228224
    float* off    = out + 2228224;       // 32*34*4096      = 4456448
    float* var    = out + 6684672;       // 32*17*4096      = 2228224
    float* fw     = out + 8912896;       // 1
    float* coords = out + 8912897;       // 32*17*2         = 1088
    float* scores = out + 8913985;       // 32*17           = 544

    dim3 blk(256);
    dim3 g256(16, 4, 32);   // row tiles, cout tiles (256/64), batch
    dim3 g128(16, 2, 32);   // cout = 128
    dim3 g1x1(16, 32);      // 4096/256 pixel tiles, batch

    // stem
    conv3x3_bn_relu<<<g256, blk>>>(x,    w_s1, g_s1, b_s1, bufA, 256, 256);
    conv3x3_bn_relu<<<g256, blk>>>(bufA, w_s2, g_s2, b_s2, bufB, 256, 256);
    // heat branch
    conv3x3_bn_relu<<<g256, blk>>>(bufB, w_h1, g_h1, b_h1, bufA, 256, 256);
    conv1x1_epi<256, 17, 0><<<g1x1, blk>>>(bufA, w_h2, c_h2, heat);
    // offset branch
    conv3x3_bn_relu<<<g256, blk>>>(bufB, w_o1, g_o1, b_o1, bufA, 256, 256);
    conv1x1_epi<256, 34, 0><<<g1x1, blk>>>(bufA, w_o2, c_o2, off);
    // variance branch
    conv3x3_bn_relu<<<g128, blk>>>(bufB, w_v1, g_v1, b_v1, bufA, 256, 128);
    conv1x1_epi<128, 17, 1><<<g1x1, blk>>>(bufA, w_v2, c_v2, var);
    // coordinate tail
    soft_argmax_kernel<<<BATCH * KPTS, 256>>>(heat, cg, scores);
    finalize_kernel<<<5, 128>>>(heat, off, cg, alpha, fusion, coords, fw);
}

// round 14
// speedup vs baseline: 2.2919x; 2.2919x over previous
#include <cuda_runtime.h>
#include <cstdint>
#include <math.h>

#define BATCH 32
#define HW    4096
#define KPTS  17

// ---------------- scratch (device globals; no allocations allowed) ----------
__device__ float g_bufA[(size_t)32 * 256 * 4096];
__device__ float g_bufB[(size_t)32 * 256 * 4096];
__device__ float g_cg[BATCH * KPTS * 2];
// transposed weights, K-major per tap: [tap][cout][cin]; hi plane + lo plane
#define WT_LO 2654208
__device__ float g_wT[2 * 2654208];

__device__ __forceinline__ float tf32r(float x) {
    float y;
    asm("cvt.rna.tf32.f32 %0, %1;" : "=f"(y) : "f"(x));
    return y;
}

// mma.sync m16n8k8 tf32: D += A*B
__device__ __forceinline__ void mma_tf32(float* d, const uint32_t* a, uint32_t b0, uint32_t b1) {
    asm volatile("mma.sync.aligned.m16n8k8.row.col.f32.tf32.tf32.f32 "
        "{%0,%1,%2,%3}, {%4,%5,%6,%7}, {%8,%9}, {%0,%1,%2,%3};"
        : "+f"(d[0]), "+f"(d[1]), "+f"(d[2]), "+f"(d[3])
        : "r"(a[0]), "r"(a[1]), "r"(a[2]), "r"(a[3]), "r"(b0), "r"(b1));
}

// ---------------- weight transpose: w[co][ci][3][3] -> wT[t][co][ci] hi/lo --
__global__ void transpose_w(const float* __restrict__ w, float* __restrict__ wTh,
                            float* __restrict__ wTl, int Cout) {
    int i = blockIdx.x * 256 + threadIdx.x;
    int total = Cout * 256 * 9;
    if (i >= total) return;
    int ci = i & 255;
    int co = (i >> 8) % Cout;
    int t  = i / (256 * Cout);
    float v = w[((size_t)co * 256 + ci) * 9 + t];
    float h = tf32r(v);
    wTh[i] = h;
    wTl[i] = tf32r(v - h);
}

// ---------------- tf32 tensor-core conv3x3 (SAME) + BN + ReLU ---------------
// CTA: 128 cout x 256 pixels (4 rows x 64 cols). K = 9 taps x Cin.
// TERMS==3: 3xTF32 split (Ah*Bh + Ah*Bl + Al*Bh) for near-fp32 accuracy.
static constexpr int STG_F = 32 * 6 * 68;            // 13056 floats per plane
static constexpr int A_F   = 128 * 36;               // 4608 floats per plane
static constexpr int SM_TOTAL = (2 * STG_F + 2 * A_F) * 4;   // 141312 bytes

template <int TERMS>
__global__ __launch_bounds__(256, 1)
void conv3x3_mma(const float* __restrict__ in,
                 const float* __restrict__ wTh, const float* __restrict__ wTl,
                 const float* __restrict__ gam, const float* __restrict__ bet,
                 float* __restrict__ out, int Cout)
{
    extern __shared__ float smem[];
    float* s_stgH = smem;                    // [cin][6][68]
    float* s_stgL = smem + STG_F;
    float* s_AH   = smem + 2 * STG_F;        // [co][36]
    float* s_AL   = s_AH + A_F;

    const int tid = threadIdx.x;
    const int lane = tid & 31;
    const int wid = tid >> 5;
    const int ln4 = lane >> 2;
    const int ln3 = lane & 3;
    const int coW = (wid & 3) * 32;
    const int pxW = (wid >> 2) * 128;

    const int rowBase = blockIdx.x * 4;
    const int b       = blockIdx.y;
    const int coBase  = blockIdx.z * 128;

    // zero halo columns (cols 64,65) in both planes
    for (int i = tid; i < 32 * 6 * 2; i += 256) {
        int ci = i / 12, r = (i % 12) >> 1, which = i & 1;
        s_stgH[ci * 408 + r * 68 + 64 + which] = 0.f;
        s_stgL[ci * 408 + r * 68 + 64 + which] = 0.f;
    }

    float acc[2][16][4];
#pragma unroll
    for (int mt = 0; mt < 2; mt++)
#pragma unroll
        for (int nt = 0; nt < 16; nt++)
#pragma unroll
            for (int q = 0; q < 4; q++) acc[mt][nt][q] = 0.f;

    const float* inB = in + (size_t)b * 256 * HW;

    // prefetch A (hi, and lo if TERMS==3) for iteration 0
    float4 aPreH[4], aPreL[4];
    {
        const float* wpH = wTh + (size_t)coBase * 256;
        const float* wpL = wTl + (size_t)coBase * 256;
#pragma unroll
        for (int j = 0; j < 4; j++) {
            int idx = tid + j * 256;
            int co = idx >> 3, k4 = idx & 7;
            aPreH[j] = *(const float4*)(wpH + co * 256 + k4 * 4);
            if (TERMS == 3) aPreL[j] = *(const float4*)(wpL + co * 256 + k4 * 4);
        }
    }

    const int aoffBase = (coW + ln4) * 36 + ln3;

    for (int it = 0; it < 72; ++it) {
        const int cb = it / 9, tap = it - cb * 9;
        const int dy = tap / 3, dx = tap - dy * 3;

        if (tap == 0) {
            __syncthreads();
            for (int i = tid; i < 3072; i += 256) {
                int q = i & 15, r = (i >> 4) % 6, ci = i / 96;
                int gy = rowBase - 1 + r;
                float4 v = make_float4(0.f, 0.f, 0.f, 0.f);
                if ((unsigned)gy < 64u)
                    v = *(const float4*)(inB + (size_t)(cb * 32 + ci) * HW + gy * 64 + q * 4);
                float4 h, l;
                h.x = tf32r(v.x); h.y = tf32r(v.y); h.z = tf32r(v.z); h.w = tf32r(v.w);
                *(float4*)(s_stgH + ci * 408 + r * 68 + q * 4) = h;
                if (TERMS == 3) {
                    l.x = tf32r(v.x - h.x); l.y = tf32r(v.y - h.y);
                    l.z = tf32r(v.z - h.z); l.w = tf32r(v.w - h.w);
                    *(float4*)(s_stgL + ci * 408 + r * 68 + q * 4) = l;
                }
            }
        }
        __syncthreads();

        // store prefetched A, then prefetch next iteration's
#pragma unroll
        for (int j = 0; j < 4; j++) {
            int idx = tid + j * 256;
            int co = idx >> 3, k4 = idx & 7;
            *(float4*)(s_AH + co * 36 + k4 * 4) = aPreH[j];
            if (TERMS == 3) *(float4*)(s_AL + co * 36 + k4 * 4) = aPreL[j];
        }
        if (it + 1 < 72) {
            int cb2 = (it + 1) / 9, tap2 = (it + 1) - cb2 * 9;
            size_t wo = ((size_t)tap2 * Cout + coBase) * 256 + cb2 * 32;
#pragma unroll
            for (int j = 0; j < 4; j++) {
                int idx = tid + j * 256;
                int co = idx >> 3, k4 = idx & 7;
                aPreH[j] = *(const float4*)(wTh + wo + co * 256 + k4 * 4);
                if (TERMS == 3) aPreL[j] = *(const float4*)(wTl + wo + co * 256 + k4 * 4);
            }
        }
        __syncthreads();

        // per-thread B offsets for this tap
        int off_n[16];
#pragma unroll
        for (int nt = 0; nt < 16; nt++) {
            int n_local = nt * 8 + ln4;
            int rr = (pxW + n_local) >> 6;
            int cc = n_local & 63;
            int x = cc + dx - 1;
            int col = (x < 0) ? 64 : ((x > 63) ? 65 : x);
            off_n[nt] = (rr + dy) * 68 + col;
        }

#pragma unroll
        for (int ks = 0; ks < 4; ks++) {
            uint32_t aH[2][4], aL[2][4];
            const int ka = aoffBase + ks * 8;
            aH[0][0] = __float_as_uint(s_AH[ka]);
            aH[0][1] = __float_as_uint(s_AH[ka + 288]);
            aH[0][2] = __float_as_uint(s_AH[ka + 4]);
            aH[0][3] = __float_as_uint(s_AH[ka + 292]);
            aH[1][0] = __float_as_uint(s_AH[ka + 576]);
            aH[1][1] = __float_as_uint(s_AH[ka + 864]);
            aH[1][2] = __float_as_uint(s_AH[ka + 580]);
            aH[1][3] = __float_as_uint(s_AH[ka + 868]);
            if (TERMS == 3) {
                aL[0][0] = __float_as_uint(s_AL[ka]);
                aL[0][1] = __float_as_uint(s_AL[ka + 288]);
                aL[0][2] = __float_as_uint(s_AL[ka + 4]);
                aL[0][3] = __float_as_uint(s_AL[ka + 292]);
                aL[1][0] = __float_as_uint(s_AL[ka + 576]);
                aL[1][1] = __float_as_uint(s_AL[ka + 864]);
                aL[1][2] = __float_as_uint(s_AL[ka + 580]);
                aL[1][3] = __float_as_uint(s_AL[ka + 868]);
            }

            const int kb = (ks * 8 + ln3) * 408;
#pragma unroll
            for (int nt = 0; nt < 16; nt++) {
                uint32_t b0h = __float_as_uint(s_stgH[kb + off_n[nt]]);
                uint32_t b1h = __float_as_uint(s_stgH[kb + 1632 + off_n[nt]]);
                mma_tf32(acc[0][nt], aH[0], b0h, b1h);
                mma_tf32(acc[1][nt], aH[1], b0h, b1h);
                if (TERMS == 3) {
                    uint32_t b0l = __float_as_uint(s_stgL[kb + off_n[nt]]);
                    uint32_t b1l = __float_as_uint(s_stgL[kb + 1632 + off_n[nt]]);
                    mma_tf32(acc[0][nt], aH[0], b0l, b1l);
                    mma_tf32(acc[1][nt], aH[1], b0l, b1l);
                    mma_tf32(acc[0][nt], aL[0], b0h, b1h);
                    mma_tf32(acc[1][nt], aL[1], b0h, b1h);
                }
            }
        }
    }

    // epilogue: BN (var = 1+eps) + ReLU, direct to gmem
    const float inv = rsqrtf(1.0f + 1e-5f);
    float* outB = out + ((size_t)b * Cout) * HW + rowBase * 64;
#pragma unroll
    for (int mt = 0; mt < 2; mt++) {
        int c0 = coBase + coW + mt * 16 + ln4;
        int c1 = c0 + 8;
        float sc0 = gam[c0] * inv, bi0 = bet[c0];
        float sc1 = gam[c1] * inv, bi1 = bet[c1];
        float* p0 = outB + (size_t)(coBase + coW + mt * 16 + ln4) * HW + pxW + 2 * ln3;
        float* p1 = p0 + 8 * HW;
#pragma unroll
        for (int nt = 0; nt < 16; nt++) {
            float2 v0, v1;
            v0.x = fmaxf(fmaf(acc[mt][nt][0], sc0, bi0), 0.f);
            v0.y = fmaxf(fmaf(acc[mt][nt][1], sc0, bi0), 0.f);
            v1.x = fmaxf(fmaf(acc[mt][nt][2], sc1, bi1), 0.f);
            v1.y = fmaxf(fmaf(acc[mt][nt][3], sc1, bi1), 0.f);
            *(float2*)(p0 + nt * 8) = v0;
            *(float2*)(p1 + nt * 8) = v1;
        }
    }
}

// ---------------- conv1x1 + bias (+ optional softplus) ----------------------
template <int CIN, int COUT, int MODE>
__global__ __launch_bounds__(256)
void conv1x1_epi(const float* __restrict__ in, const float* __restrict__ w,
                 const float* __restrict__ bias, float* __restrict__ out)
{
    __shared__ float s_w[COUT * CIN];
    const int tid = threadIdx.x;
    for (int i = tid; i < COUT * CIN; i += 256) s_w[i] = w[i];
    __syncthreads();

    const int p = blockIdx.x * 256 + tid;
    const int b = blockIdx.y;

    float acc[COUT];
#pragma unroll
    for (int k = 0; k < COUT; k++) acc[k] = 0.f;

    const float* ip = in + (size_t)b * CIN * HW + p;
#pragma unroll 4
    for (int c = 0; c < CIN; c++) {
        float v = ip[(size_t)c * HW];
#pragma unroll
        for (int k = 0; k < COUT; k++) acc[k] = fmaf(v, s_w[k * CIN + c], acc[k]);
    }
#pragma unroll
    for (int k = 0; k < COUT; k++) {
        float v = acc[k] + bias[k];
        if (MODE == 1) v = fmaxf(v, 0.f) + log1pf(expf(-fabsf(v)));
        out[((size_t)b * COUT + k) * HW + p] = v;
    }
}

// ---------------- soft-argmax over 64x64 heatmap per (b,k) ------------------
__global__ void soft_argmax_kernel(const float* __restrict__ heat,
                                   float* __restrict__ cg,
                                   float* __restrict__ scores)
{
    const int bk  = blockIdx.x;
    const int tid = threadIdx.x;
    const float* h = heat + (size_t)bk * HW;
    __shared__ float rs0[256], rs1[256], rs2[256];

    float m = -INFINITY;
    for (int p = tid; p < HW; p += 256) m = fmaxf(m, h[p]);
    rs0[tid] = m;
    __syncthreads();
    for (int s = 128; s > 0; s >>= 1) {
        if (tid < s) rs0[tid] = fmaxf(rs0[tid], rs0[tid + s]);
        __syncthreads();
    }
    const float mx = rs0[0];
    __syncthreads();

    float se = 0.f, sx = 0.f, sy = 0.f;
    for (int p = tid; p < HW; p += 256) {
        float e = expf(h[p] - mx);
        se += e; sx += e * (float)(p & 63); sy += e * (float)(p >> 6);
    }
    rs0[tid] = se; rs1[tid] = sx; rs2[tid] = sy;
    __syncthreads();
    for (int s = 128; s > 0; s >>= 1) {
        if (tid < s) { rs0[tid] += rs0[tid+s]; rs1[tid] += rs1[tid+s]; rs2[tid] += rs2[tid+s]; }
        __syncthreads();
    }
    if (tid == 0) {
        scores[bk] = mx;
        cg[2*bk]   = rs1[0] / rs0[0];
        cg[2*bk+1] = rs2[0] / rs0[0];
    }
}

// ---------------- local refine + combine + offset sampling ------------------
__global__ void finalize_kernel(const float* __restrict__ heat,
                                const float* __restrict__ off,
                                const float* __restrict__ cg,
                                const float* __restrict__ alpha_p,
                                const float* __restrict__ fusion_p,
                                float* __restrict__ coords,
                                float* __restrict__ fw_out)
{
    const int t = blockIdx.x * blockDim.x + threadIdx.x;
    const float fwv = 1.f / (1.f + expf(-fusion_p[0]));
    if (t == 0) fw_out[0] = fwv;
    if (t >= BATCH * KPTS) return;

    const float a   = 1.f / (1.f + expf(-alpha_p[0]));
    const float cgx = cg[2*t], cgy = cg[2*t+1];
    const int px = (int)rintf(fminf(fmaxf(cgx, 0.f), 63.f));
    const int py = (int)rintf(fminf(fmaxf(cgy, 0.f), 63.f));
    const float* h = heat + (size_t)t * HW;

    float mx = -INFINITY;
    for (int i = 0; i < 5; i++) {
        int ys = py + i - 2; if ((unsigned)ys >= 64u) continue;
        for (int j = 0; j < 5; j++) {
            int xs = px + j - 2; if ((unsigned)xs >= 64u) continue;
            mx = fmaxf(mx, h[ys*64 + xs]);
        }
    }
    float sw = 0.f, sxw = 0.f, syw = 0.f;
    for (int i = 0; i < 5; i++) {
        int ys = py + i - 2; if ((unsigned)ys >= 64u) continue;
        for (int j = 0; j < 5; j++) {
            int xs = px + j - 2; if ((unsigned)xs >= 64u) continue;
            float e = expf(h[ys*64 + xs] - mx);
            sw += e; sxw += e * (float)xs; syw += e * (float)ys;
        }
    }
    float cx = a * cgx + (1.f - a) * (sxw / sw);
    float cy = a * cgy + (1.f - a) * (syw / sw);

    const float ix = fminf(fmaxf(cx, 0.f), 63.f);
    const float iy = fminf(fmaxf(cy, 0.f), 63.f);
    const float x0 = floorf(ix), y0 = floorf(iy);
    const float wx = ix - x0,  wy = iy - y0;
    const int x0i = min(max((int)x0, 0), 63), x1i = min(x0i + 1, 63);
    const int y0i = min(max((int)y0, 0), 63), y1i = min(y0i + 1, 63);

    const float* o0 = off + (size_t)(t * 2) * HW;
    const float* o1 = o0 + HW;
    float a00 = o0[y0i*64+x0i], a01 = o0[y0i*64+x1i], a10 = o0[y1i*64+x0i], a11 = o0[y1i*64+x1i];
    float v0 = (1.f-wy)*((1.f-wx)*a00 + wx*a01) + wy*((1.f-wx)*a10 + wx*a11);
    a00 = o1[y0i*64+x0i]; a01 = o1[y0i*64+x1i]; a10 = o1[y1i*64+x0i]; a11 = o1[y1i*64+x1i];
    float v1 = (1.f-wy)*((1.f-wx)*a00 + wx*a01) + wy*((1.f-wx)*a10 + wx*a11);

    coords[2*t]   = cx + fwv * v0;
    coords[2*t+1] = cy + fwv * v1;
}

// ---------------- launch ----------------------------------------------------
extern "C" void kernel_launch(void* const* d_in, const int* in_sizes, int n_in,
                              void* d_out, int out_size)
{
    const float* x    = (const float*)d_in[0];
    const float* w_s1 = (const float*)d_in[1];
    const float* g_s1 = (const float*)d_in[2];
    const float* b_s1 = (const float*)d_in[3];
    const float* w_s2 = (const float*)d_in[4];
    const float* g_s2 = (const float*)d_in[5];
    const float* b_s2 = (const float*)d_in[6];
    const float* w_h1 = (const float*)d_in[7];
    const float* g_h1 = (const float*)d_in[8];
    const float* b_h1 = (const float*)d_in[9];
    const float* w_h2 = (const float*)d_in[10];
    const float* c_h2 = (const float*)d_in[11];
    const float* w_o1 = (const float*)d_in[12];
    const float* g_o1 = (const float*)d_in[13];
    const float* b_o1 = (const float*)d_in[14];
    const float* w_o2 = (const float*)d_in[15];
    const float* c_o2 = (const float*)d_in[16];
    const float* w_v1 = (const float*)d_in[17];
    const float* g_v1 = (const float*)d_in[18];
    const float* b_v1 = (const float*)d_in[19];
    const float* w_v2 = (const float*)d_in[20];
    const float* c_v2 = (const float*)d_in[21];
    const float* alpha  = (const float*)d_in[22];
    const float* fusion = (const float*)d_in[23];

    float *bufA, *bufB, *cg, *wT;
    cudaGetSymbolAddress((void**)&bufA, g_bufA);
    cudaGetSymbolAddress((void**)&bufB, g_bufB);
    cudaGetSymbolAddress((void**)&cg,   g_cg);
    cudaGetSymbolAddress((void**)&wT,   g_wT);

    float* wTh_s1 = wT;
    float* wTh_s2 = wT +  589824;
    float* wTh_h1 = wT + 1179648;
    float* wTh_o1 = wT + 1769472;
    float* wTh_v1 = wT + 2359296;
    float* wTl_s1 = wTh_s1 + WT_LO;
    float* wTl_s2 = wTh_s2 + WT_LO;
    float* wTl_h1 = wTh_h1 + WT_LO;
    float* wTl_o1 = wTh_o1 + WT_LO;
    float* wTl_v1 = wTh_v1 + WT_LO;

    float* out    = (float*)d_out;
    float* heat   = out;
    float* off    = out + 2228224;
    float* var    = out + 6684672;
    float* fw     = out + 8912896;
    float* coords = out + 8912897;
    float* scores = out + 8913985;

    cudaFuncSetAttribute(conv3x3_mma<3>, cudaFuncAttributeMaxDynamicSharedMemorySize, SM_TOTAL);
    cudaFuncSetAttribute(conv3x3_mma<1>, cudaFuncAttributeMaxDynamicSharedMemorySize, SM_TOTAL);

    dim3 blk(256);
    dim3 gT((256 * 256 * 9 + 255) / 256);
    dim3 gTv((128 * 256 * 9 + 255) / 256);
    transpose_w<<<gT,  blk>>>(w_s1, wTh_s1, wTl_s1, 256);
    transpose_w<<<gT,  blk>>>(w_s2, wTh_s2, wTl_s2, 256);
    transpose_w<<<gT,  blk>>>(w_h1, wTh_h1, wTl_h1, 256);
    transpose_w<<<gT,  blk>>>(w_o1, wTh_o1, wTl_o1, 256);
    transpose_w<<<gTv, blk>>>(w_v1, wTh_v1, wTl_v1, 128);

    dim3 gC2(16, 32, 2);   // rowgroups, batch, cout halves
    dim3 gC1(16, 32, 1);
    dim3 g1x1(16, 32);

    conv3x3_mma<3><<<gC2, blk, SM_TOTAL>>>(x,    wTh_s1, wTl_s1, g_s1, b_s1, bufA, 256);
    conv3x3_mma<3><<<gC2, blk, SM_TOTAL>>>(bufA, wTh_s2, wTl_s2, g_s2, b_s2, bufB, 256);
    conv3x3_mma<3><<<gC2, blk, SM_TOTAL>>>(bufB, wTh_h1, wTl_h1, g_h1, b_h1, bufA, 256);
    conv1x1_epi<256, 17, 0><<<g1x1, blk>>>(bufA, w_h2, c_h2, heat);
    conv3x3_mma<1><<<gC2, blk, SM_TOTAL>>>(bufB, wTh_o1, wTl_o1, g_o1, b_o1, bufA, 256);
    conv1x1_epi<256, 34, 0><<<g1x1, blk>>>(bufA, w_o2, c_o2, off);
    conv3x3_mma<1><<<gC1, blk, SM_TOTAL>>>(bufB, wTh_v1, wTl_v1, g_v1, b_v1, bufA, 128);
    conv1x1_epi<128, 17, 1><<<g1x1, blk>>>(bufA, w_v2, c_v2, var);

    soft_argmax_kernel<<<BATCH * KPTS, 256>>>(heat, cg, scores);
    finalize_kernel<<<5, 128>>>(heat, off, cg, alpha, fusion, coords, fw);
}